// round 9
// baseline (speedup 1.0000x reference)
#include <cuda_runtime.h>
#include <cuda_fp16.h>
#include <cstdint>

#define D 64
#define H 128
#define NMAX 50048

// Node-factored layer-1 preactivations, fp16 (halves gather traffic)
__device__ __align__(16) __half g_P[(size_t)NMAX * H];
__device__ __align__(16) __half g_Q[(size_t)NMAX * H];
__device__ int g_ctr_pre;    // reset by edge_kernel (for next replay)
__device__ int g_ctr_edge;   // reset by precompute_kernel (runs first)

__device__ __forceinline__ float sigt(float x) {
    float t;
    asm("tanh.approx.f32 %0, %1;" : "=f"(t) : "f"(x * 0.5f));
    return fmaf(t, 0.5f, 0.5f);
}
__device__ __forceinline__ uint32_t f16x2(float lo, float hi) {
    __half2 h = __floats2half2_rn(lo, hi);
    return *(uint32_t*)&h;
}
__device__ __forceinline__ float2 h2f2(__half2 h) { return __half22float2(h); }
__device__ __forceinline__ __half2 u2h2(uint32_t u) { return *(__half2*)&u; }

// fp16 m16n8k16 row.col MMA, fp32 accum
__device__ __forceinline__ void mma_f16(float* c, uint4 a, uint2 b) {
    asm volatile(
        "mma.sync.aligned.m16n8k16.row.col.f32.f16.f16.f32 "
        "{%0,%1,%2,%3}, {%4,%5,%6,%7}, {%8,%9}, {%0,%1,%2,%3};"
        : "+f"(c[0]), "+f"(c[1]), "+f"(c[2]), "+f"(c[3])
        : "r"(a.x), "r"(a.y), "r"(a.z), "r"(a.w), "r"(b.x), "r"(b.y));
}

// Build fp16 A-fragments (m16n8k16 row-major layout, validated R5-R8) from a
// 32-row fp32 scratch slab, ncols = nkt*16.
__device__ __forceinline__ void build_frags_h(const float* scr, uint4* A,
                                              int mt_base, int nkt, int t, int nth)
{
    const int ncols = nkt * 16;
    for (int fid = t; fid < 64 * nkt; fid += nth) {
        int fl = fid & 31;
        int kt = (fid >> 5) % nkt;
        int mtl = fid / (32 * nkt);
        int fg = fl >> 2, ft = fl & 3;
        int lr0 = mtl * 16 + fg, lr1 = lr0 + 8;
        int k0 = kt * 16 + ft * 2;
        uint4 hi;
        hi.x = f16x2(scr[lr0 * ncols + k0],     scr[lr0 * ncols + k0 + 1]);
        hi.y = f16x2(scr[lr1 * ncols + k0],     scr[lr1 * ncols + k0 + 1]);
        hi.z = f16x2(scr[lr0 * ncols + k0 + 8], scr[lr0 * ncols + k0 + 9]);
        hi.w = f16x2(scr[lr1 * ncols + k0 + 8], scr[lr1 * ncols + k0 + 9]);
        A[((mt_base + mtl) * nkt + kt) * 32 + fl] = hi;
    }
}

// Stage 4 consecutive-k values (k%4==0) for fragment-column nn of group nt.
// Writer XOR = e>>2; reader uses lane ^ (2*nt + lane>>4). Validated R6-R8.
__device__ __forceinline__ void stage4h(uint32_t* B, int nt, int nn, int xe, int k,
                                        float z0, float z1, float z2, float z3)
{
    uint32_t h01 = f16x2(z0, z1);
    uint32_t h23 = f16x2(z2, z3);
    int kt = k >> 4, kq = (k & 7) >> 1, reg = (k >> 3) & 1;
    int l0 = (nn * 4 + kq) ^ xe, l1 = (nn * 4 + kq + 1) ^ xe;
    int base = (nt * 8 + kt) * 64;
    B[base + l0 * 2 + reg] = h01;
    B[base + l1 * 2 + reg] = h23;
}

// ---------------------------------------------------------------------------
// Precompute: P[n] = b1 + [Wa | Wc+Wd] @ [h1;h2],  Q[n] = Wb @ h1  (fp16 out)
// 256 threads, 8 independent warps, 32 nodes per warp-tile, fp16 HMMA.
// ---------------------------------------------------------------------------
#define P_A1 0                  // 32 KB
#define P_A2 32768              // 16 KB
#define P_B  49152              // 8 warps x 8 KB
#define P_B1S 114688
#define PRE_SMEM_BYTES 115712

__global__ void __launch_bounds__(256) precompute_kernel(
    const float* __restrict__ h1, const float* __restrict__ h2,
    const float* __restrict__ W1, const float* __restrict__ b1, int n)
{
    extern __shared__ char smc[];
    uint4* A1 = (uint4*)(smc + P_A1);
    uint4* A2 = (uint4*)(smc + P_A2);
    float* b1s = (float*)(smc + P_B1S);

    const int t = threadIdx.x, lane = t & 31, w = t >> 5;
    const int gid = lane >> 2, tig = lane & 3;

    if (blockIdx.x == 0 && t == 0) g_ctr_edge = 0;   // reset for edge_kernel

    {
        float* scr = (float*)(smc + P_B);
        for (int chunk = 0; chunk < 4; ++chunk) {
            const int R0 = chunk * 32;
            __syncthreads();
            for (int idx = t; idx < 4096; idx += 256) {
                int r = idx >> 7, k = idx & 127;
                float v;
                if (k < 64) v = W1[(R0 + r) * 256 + k];
                else        v = W1[(R0 + r) * 256 + 64 + k] + W1[(R0 + r) * 256 + 128 + k];
                scr[r * 128 + k] = v;
            }
            __syncthreads();
            build_frags_h(scr, A1, chunk * 2, 8, t, 256);
        }
        for (int chunk = 0; chunk < 4; ++chunk) {
            const int R0 = chunk * 32;
            __syncthreads();
            for (int idx = t; idx < 2048; idx += 256) {
                int r = idx >> 6, k = idx & 63;
                scr[r * 64 + k] = W1[(R0 + r) * 256 + 64 + k];
            }
            __syncthreads();
            build_frags_h(scr, A2, chunk * 2, 4, t, 256);
        }
    }
    if (t < 128) b1s[t] = b1[t];
    __syncthreads();

    float b1r0[8], b1r1[8];
    #pragma unroll
    for (int mt = 0; mt < 8; ++mt) {
        b1r0[mt] = b1s[mt * 16 + gid];
        b1r1[mt] = b1s[mt * 16 + gid + 8];
    }

    uint32_t* Bw = (uint32_t*)(smc + P_B + w * 8192);
    const int e = lane, nt_e = e >> 3, n_e = e & 7, xe = e >> 2;
    const int lq = lane >> 4;
    const int ntiles = (n + 31) >> 5;

    for (;;) {
        int tile;
        if (lane == 0) tile = atomicAdd(&g_ctr_pre, 1);
        tile = __shfl_sync(0xffffffffu, tile, 0);
        if (tile >= ntiles) break;
        const int nb = tile * 32;
        const int node = nb + e;
        __syncwarp();

        if (node < n) {
            const float4* H1 = (const float4*)(h1 + (size_t)node * D);
            const float4* H2 = (const float4*)(h2 + (size_t)node * D);
            #pragma unroll 8
            for (int u = 0; u < 16; ++u) {
                float4 v = H1[u];
                stage4h(Bw, nt_e, n_e, xe, u * 4, v.x, v.y, v.z, v.w);
            }
            #pragma unroll 8
            for (int u = 0; u < 16; ++u) {
                float4 v = H2[u];
                stage4h(Bw, nt_e, n_e, xe, 64 + u * 4, v.x, v.y, v.z, v.w);
            }
        } else {
            #pragma unroll 8
            for (int u = 0; u < 32; ++u)
                stage4h(Bw, nt_e, n_e, xe, u * 4, 0.f, 0.f, 0.f, 0.f);
        }
        __syncwarp();

        float acc[8][4][4];

        // ---- P pass: A1, K=128
        #pragma unroll
        for (int mt = 0; mt < 8; ++mt)
            #pragma unroll
            for (int nt = 0; nt < 4; ++nt)
                #pragma unroll
                for (int r = 0; r < 4; ++r) acc[mt][nt][r] = 0.f;

        #pragma unroll 1
        for (int kt = 0; kt < 8; ++kt) {
            uint2 bh[4];
            #pragma unroll
            for (int nt = 0; nt < 4; ++nt)
                bh[nt] = ((const uint2*)Bw)[(nt * 8 + kt) * 32 + (lane ^ (2 * nt + lq))];
            #pragma unroll
            for (int mt = 0; mt < 8; ++mt) {
                uint4 ah = A1[(mt * 8 + kt) * 32 + lane];
                #pragma unroll
                for (int nt = 0; nt < 4; ++nt) mma_f16(acc[mt][nt], ah, bh[nt]);
            }
        }
        #pragma unroll
        for (int nt = 0; nt < 4; ++nt) {
            int n0 = nb + nt * 8 + tig * 2, n1 = n0 + 1;
            #pragma unroll
            for (int mt = 0; mt < 8; ++mt) {
                int r0 = mt * 16 + gid, r1 = r0 + 8;
                if (n0 < n) {
                    g_P[(size_t)n0 * H + r0] = __float2half_rn(acc[mt][nt][0] + b1r0[mt]);
                    g_P[(size_t)n0 * H + r1] = __float2half_rn(acc[mt][nt][2] + b1r1[mt]);
                }
                if (n1 < n) {
                    g_P[(size_t)n1 * H + r0] = __float2half_rn(acc[mt][nt][1] + b1r0[mt]);
                    g_P[(size_t)n1 * H + r1] = __float2half_rn(acc[mt][nt][3] + b1r1[mt]);
                }
            }
        }

        // ---- Q pass: A2, K=64 (B slabs kt 0..3 hold h1)
        #pragma unroll
        for (int mt = 0; mt < 8; ++mt)
            #pragma unroll
            for (int nt = 0; nt < 4; ++nt)
                #pragma unroll
                for (int r = 0; r < 4; ++r) acc[mt][nt][r] = 0.f;

        #pragma unroll 1
        for (int kt = 0; kt < 4; ++kt) {
            uint2 bh[4];
            #pragma unroll
            for (int nt = 0; nt < 4; ++nt)
                bh[nt] = ((const uint2*)Bw)[(nt * 8 + kt) * 32 + (lane ^ (2 * nt + lq))];
            #pragma unroll
            for (int mt = 0; mt < 8; ++mt) {
                uint4 ah = A2[(mt * 4 + kt) * 32 + lane];
                #pragma unroll
                for (int nt = 0; nt < 4; ++nt) mma_f16(acc[mt][nt], ah, bh[nt]);
            }
        }
        #pragma unroll
        for (int nt = 0; nt < 4; ++nt) {
            int n0 = nb + nt * 8 + tig * 2, n1 = n0 + 1;
            #pragma unroll
            for (int mt = 0; mt < 8; ++mt) {
                int r0 = mt * 16 + gid, r1 = r0 + 8;
                if (n0 < n) {
                    g_Q[(size_t)n0 * H + r0] = __float2half_rn(acc[mt][nt][0]);
                    g_Q[(size_t)n0 * H + r1] = __float2half_rn(acc[mt][nt][2]);
                }
                if (n1 < n) {
                    g_Q[(size_t)n1 * H + r0] = __float2half_rn(acc[mt][nt][1]);
                    g_Q[(size_t)n1 * H + r1] = __float2half_rn(acc[mt][nt][3]);
                }
            }
        }
    }
}

// ---------------------------------------------------------------------------
// Edge kernel: 128-thread blocks (4 warps), __launch_bounds__(128,3) for
// 3 blocks/SM = 12 warps. Warp-independent 32-edge tiles, 2 tiles/ticket.
// ---------------------------------------------------------------------------
#define E_A   0                 // 32 KB
#define E_B   32768             // 4 warps x 8 KB
#define E_B2S 65536
#define E_W3S 66048
#define EDGE_SMEM_BYTES 66560

__global__ void __launch_bounds__(128, 3) edge_kernel(
    const int* __restrict__ src, const int* __restrict__ dst,
    const float* __restrict__ W2, const float* __restrict__ b2,
    const float* __restrict__ W3, const float* __restrict__ b3,
    float* __restrict__ out, int E, int n)
{
    extern __shared__ char smc[];
    uint4* Ahi = (uint4*)(smc + E_A);
    float* b2s = (float*)(smc + E_B2S);
    float* w3s = (float*)(smc + E_W3S);

    const int t = threadIdx.x, lane = t & 31, w = t >> 5;
    const int gid = lane >> 2, tig = lane & 3;

    if (blockIdx.x == 0 && t == 0) g_ctr_pre = 0;    // reset for next replay

    // Build W2 fp16 fragments once (scratch reuses B region: 16KB < 32KB).
    {
        float* scr = (float*)(smc + E_B);
        for (int chunk = 0; chunk < 4; ++chunk) {
            __syncthreads();
            for (int i = t; i < 1024; i += 128)
                ((float4*)scr)[i] = ((const float4*)W2)[chunk * 1024 + i];
            __syncthreads();
            build_frags_h(scr, Ahi, chunk * 2, 8, t, 128);
        }
    }
    b2s[t] = b2[t];
    w3s[t] = W3[t];
    __syncthreads();

    float b2r0[8], b2r1[8], w3r0[8], w3r1[8];
    #pragma unroll
    for (int mt = 0; mt < 8; ++mt) {
        b2r0[mt] = b2s[mt * 16 + gid];
        b2r1[mt] = b2s[mt * 16 + gid + 8];
        w3r0[mt] = w3s[mt * 16 + gid];
        w3r1[mt] = w3s[mt * 16 + gid + 8];
    }
    const float b3v = b3[0];

    uint32_t* Bw = (uint32_t*)(smc + E_B + w * 8192);
    const int e = lane, nt_e = e >> 3, n_e = e & 7, xe = e >> 2;
    const int lq = lane >> 4;
    const int ntiles = (E + 31) >> 5;

    for (;;) {
        int tk;
        if (lane == 0) tk = atomicAdd(&g_ctr_edge, 2);   // 2 tiles per ticket
        tk = __shfl_sync(0xffffffffu, tk, 0);
        if (tk >= ntiles) break;

        #pragma unroll 1
        for (int sub = 0; sub < 2; ++sub) {
            const int tile = tk + sub;
            if (tile >= ntiles) break;
            const int e0 = tile * 32;
            const int ge = e0 + e;
            __syncwarp();

            // stage z1 = sigmoid(P[src] + Q[dst]); P+Q added in fp16 (HADD2)
            if (ge < E) {
                int s = min(max(src[ge], 0), n - 1);
                int d = min(max(dst[ge], 0), n - 1);
                const uint4* Pp = (const uint4*)(g_P + (size_t)s * H);
                const uint4* Qp = (const uint4*)(g_Q + (size_t)d * H);
                #pragma unroll 4
                for (int u = 0; u < 16; ++u) {
                    uint4 pv = Pp[u], qv = Qp[u];
                    float2 f0 = h2f2(__hadd2(u2h2(pv.x), u2h2(qv.x)));
                    float2 f1 = h2f2(__hadd2(u2h2(pv.y), u2h2(qv.y)));
                    float2 f2 = h2f2(__hadd2(u2h2(pv.z), u2h2(qv.z)));
                    float2 f3 = h2f2(__hadd2(u2h2(pv.w), u2h2(qv.w)));
                    stage4h(Bw, nt_e, n_e, xe, u * 8,
                            sigt(f0.x), sigt(f0.y), sigt(f1.x), sigt(f1.y));
                    stage4h(Bw, nt_e, n_e, xe, u * 8 + 4,
                            sigt(f2.x), sigt(f2.y), sigt(f3.x), sigt(f3.y));
                }
            } else {
                #pragma unroll 8
                for (int u = 0; u < 32; ++u)
                    stage4h(Bw, nt_e, n_e, xe, u * 4, 0.f, 0.f, 0.f, 0.f);
            }
            __syncwarp();

            float acc[8][4][4];
            #pragma unroll
            for (int mt = 0; mt < 8; ++mt)
                #pragma unroll
                for (int nt = 0; nt < 4; ++nt)
                    #pragma unroll
                    for (int r = 0; r < 4; ++r) acc[mt][nt][r] = 0.f;

            #pragma unroll 1
            for (int kt = 0; kt < 8; ++kt) {
                uint2 bh[4];
                #pragma unroll
                for (int nt = 0; nt < 4; ++nt)
                    bh[nt] = ((const uint2*)Bw)[(nt * 8 + kt) * 32 + (lane ^ (2 * nt + lq))];
                #pragma unroll
                for (int mt = 0; mt < 8; ++mt) {
                    uint4 ah = Ahi[(mt * 8 + kt) * 32 + lane];
                    #pragma unroll
                    for (int nt = 0; nt < 4; ++nt) mma_f16(acc[mt][nt], ah, bh[nt]);
                }
            }

            // epilogue: sigmoid + W3 dot, reduce over gid (lane bits 2..4)
            #pragma unroll
            for (int nt = 0; nt < 4; ++nt) {
                float s0 = 0.f, s1 = 0.f;
                #pragma unroll
                for (int mt = 0; mt < 8; ++mt) {
                    s0 += sigt(acc[mt][nt][0] + b2r0[mt]) * w3r0[mt]
                        + sigt(acc[mt][nt][2] + b2r1[mt]) * w3r1[mt];
                    s1 += sigt(acc[mt][nt][1] + b2r0[mt]) * w3r0[mt]
                        + sigt(acc[mt][nt][3] + b2r1[mt]) * w3r1[mt];
                }
                #pragma unroll
                for (int off = 4; off <= 16; off <<= 1) {
                    s0 += __shfl_xor_sync(0xffffffffu, s0, off);
                    s1 += __shfl_xor_sync(0xffffffffu, s1, off);
                }
                if (gid == 0) {
                    int go = e0 + nt * 8 + tig * 2;
                    if (go + 1 < E)
                        *(float2*)(out + go) = make_float2(s0 + b3v, s1 + b3v);
                    else if (go < E)
                        out[go] = s0 + b3v;
                }
            }
        }
    }
}

extern "C" void kernel_launch(void* const* d_in, const int* in_sizes, int n_in,
                              void* d_out, int out_size)
{
    const float* h1 = (const float*)d_in[0];
    const float* h2 = (const float*)d_in[1];
    const int* src = (const int*)d_in[2];
    const int* dst = (const int*)d_in[3];
    const float* W1 = (const float*)d_in[4];
    const float* b1 = (const float*)d_in[5];
    const float* W2 = (const float*)d_in[6];
    const float* b2 = (const float*)d_in[7];
    const float* W3 = (const float*)d_in[8];
    const float* b3 = (const float*)d_in[9];
    float* out = (float*)d_out;

    const int n = in_sizes[0] / D;
    const int E = in_sizes[2];

    cudaFuncSetAttribute(precompute_kernel,
                         cudaFuncAttributeMaxDynamicSharedMemorySize, PRE_SMEM_BYTES);
    cudaFuncSetAttribute(edge_kernel,
                         cudaFuncAttributeMaxDynamicSharedMemorySize, EDGE_SMEM_BYTES);

    precompute_kernel<<<148, 256, PRE_SMEM_BYTES>>>(h1, h2, W1, b1, n);
    edge_kernel<<<444, 128, EDGE_SMEM_BYTES>>>(src, dst, W2, b2, W3, b3, out, E, n);
}

// round 10
// speedup vs baseline: 1.1295x; 1.1295x over previous
#include <cuda_runtime.h>
#include <cuda_fp16.h>
#include <cstdint>

#define D 64
#define H 128
#define NMAX 50048

// Node-factored layer-1 preactivations, fp16 (halves gather traffic)
__device__ __align__(16) __half g_P[(size_t)NMAX * H];
__device__ __align__(16) __half g_Q[(size_t)NMAX * H];
__device__ int g_ctr_pre;    // reset by edge_kernel (for next replay)
__device__ int g_ctr_edge;   // reset by precompute_kernel (runs first)

__device__ __forceinline__ float sigt(float x) {
    float t;
    asm("tanh.approx.f32 %0, %1;" : "=f"(t) : "f"(x * 0.5f));
    return fmaf(t, 0.5f, 0.5f);
}
// half2 sigmoid: sig(x) = 0.5*tanh(0.5x)+0.5, fully in f16x2 (3 instr / 2 vals)
__device__ __forceinline__ uint32_t sigt2u(uint32_t p, uint32_t q) {
    __half2 x = __hadd2(*(__half2*)&p, *(__half2*)&q);
    const __half2 hhalf = __floats2half2_rn(0.5f, 0.5f);
    __half2 xh = __hmul2(x, hhalf);
    uint32_t tu;
    asm("tanh.approx.f16x2 %0, %1;" : "=r"(tu) : "r"(*(uint32_t*)&xh));
    __half2 r = __hfma2(*(__half2*)&tu, hhalf, hhalf);
    return *(uint32_t*)&r;
}
__device__ __forceinline__ uint32_t f16x2(float lo, float hi) {
    __half2 h = __floats2half2_rn(lo, hi);
    return *(uint32_t*)&h;
}

// fp16 m16n8k16 row.col MMA, fp32 accum
__device__ __forceinline__ void mma_f16(float* c, uint4 a, uint2 b) {
    asm volatile(
        "mma.sync.aligned.m16n8k16.row.col.f32.f16.f16.f32 "
        "{%0,%1,%2,%3}, {%4,%5,%6,%7}, {%8,%9}, {%0,%1,%2,%3};"
        : "+f"(c[0]), "+f"(c[1]), "+f"(c[2]), "+f"(c[3])
        : "r"(a.x), "r"(a.y), "r"(a.z), "r"(a.w), "r"(b.x), "r"(b.y));
}

// Build fp16 A-fragments (m16n8k16 row-major layout, validated R5-R9) from a
// 32-row fp32 scratch slab, ncols = nkt*16.
__device__ __forceinline__ void build_frags_h(const float* scr, uint4* A,
                                              int mt_base, int nkt, int t, int nth)
{
    const int ncols = nkt * 16;
    for (int fid = t; fid < 64 * nkt; fid += nth) {
        int fl = fid & 31;
        int kt = (fid >> 5) % nkt;
        int mtl = fid / (32 * nkt);
        int fg = fl >> 2, ft = fl & 3;
        int lr0 = mtl * 16 + fg, lr1 = lr0 + 8;
        int k0 = kt * 16 + ft * 2;
        uint4 hi;
        hi.x = f16x2(scr[lr0 * ncols + k0],     scr[lr0 * ncols + k0 + 1]);
        hi.y = f16x2(scr[lr1 * ncols + k0],     scr[lr1 * ncols + k0 + 1]);
        hi.z = f16x2(scr[lr0 * ncols + k0 + 8], scr[lr0 * ncols + k0 + 9]);
        hi.w = f16x2(scr[lr1 * ncols + k0 + 8], scr[lr1 * ncols + k0 + 9]);
        A[((mt_base + mtl) * nkt + kt) * 32 + fl] = hi;
    }
}

// Store two packed f16x2 words (k%4==0: values k..k+3) for fragment-column nn
// of group nt. Writer XOR = e>>2; reader uses lane ^ (2*nt + lane>>4). R6-R9.
__device__ __forceinline__ void stage4u(uint32_t* B, int nt, int nn, int xe, int k,
                                        uint32_t h01, uint32_t h23)
{
    int kt = k >> 4, kq = (k & 7) >> 1, reg = (k >> 3) & 1;
    int l0 = (nn * 4 + kq) ^ xe, l1 = (nn * 4 + kq + 1) ^ xe;
    int base = (nt * 8 + kt) * 64;
    B[base + l0 * 2 + reg] = h01;
    B[base + l1 * 2 + reg] = h23;
}
__device__ __forceinline__ void stage4h(uint32_t* B, int nt, int nn, int xe, int k,
                                        float z0, float z1, float z2, float z3)
{
    stage4u(B, nt, nn, xe, k, f16x2(z0, z1), f16x2(z2, z3));
}

// ---------------------------------------------------------------------------
// Precompute: P[n] = b1 + [Wa | Wc+Wd] @ [h1;h2],  Q[n] = Wb @ h1  (fp16 out)
// 256 threads, 8 independent warps, 32 nodes per warp-tile, fp16 HMMA.
// ---------------------------------------------------------------------------
#define P_A1 0                  // 32 KB
#define P_A2 32768              // 16 KB
#define P_B  49152              // 8 warps x 8 KB
#define P_B1S 114688
#define PRE_SMEM_BYTES 115712

__global__ void __launch_bounds__(256) precompute_kernel(
    const float* __restrict__ h1, const float* __restrict__ h2,
    const float* __restrict__ W1, const float* __restrict__ b1, int n)
{
    extern __shared__ char smc[];
    uint4* A1 = (uint4*)(smc + P_A1);
    uint4* A2 = (uint4*)(smc + P_A2);
    float* b1s = (float*)(smc + P_B1S);

    const int t = threadIdx.x, lane = t & 31, w = t >> 5;
    const int gid = lane >> 2, tig = lane & 3;

    if (blockIdx.x == 0 && t == 0) g_ctr_edge = 0;   // reset for edge_kernel

    {
        float* scr = (float*)(smc + P_B);
        for (int chunk = 0; chunk < 4; ++chunk) {
            const int R0 = chunk * 32;
            __syncthreads();
            for (int idx = t; idx < 4096; idx += 256) {
                int r = idx >> 7, k = idx & 127;
                float v;
                if (k < 64) v = W1[(R0 + r) * 256 + k];
                else        v = W1[(R0 + r) * 256 + 64 + k] + W1[(R0 + r) * 256 + 128 + k];
                scr[r * 128 + k] = v;
            }
            __syncthreads();
            build_frags_h(scr, A1, chunk * 2, 8, t, 256);
        }
        for (int chunk = 0; chunk < 4; ++chunk) {
            const int R0 = chunk * 32;
            __syncthreads();
            for (int idx = t; idx < 2048; idx += 256) {
                int r = idx >> 6, k = idx & 63;
                scr[r * 64 + k] = W1[(R0 + r) * 256 + 64 + k];
            }
            __syncthreads();
            build_frags_h(scr, A2, chunk * 2, 4, t, 256);
        }
    }
    if (t < 128) b1s[t] = b1[t];
    __syncthreads();

    float b1r0[8], b1r1[8];
    #pragma unroll
    for (int mt = 0; mt < 8; ++mt) {
        b1r0[mt] = b1s[mt * 16 + gid];
        b1r1[mt] = b1s[mt * 16 + gid + 8];
    }

    uint32_t* Bw = (uint32_t*)(smc + P_B + w * 8192);
    const int e = lane, nt_e = e >> 3, n_e = e & 7, xe = e >> 2;
    const int lq = lane >> 4;
    const int ntiles = (n + 31) >> 5;

    for (;;) {
        int tile;
        if (lane == 0) tile = atomicAdd(&g_ctr_pre, 1);
        tile = __shfl_sync(0xffffffffu, tile, 0);
        if (tile >= ntiles) break;
        const int nb = tile * 32;
        const int node = nb + e;
        __syncwarp();

        if (node < n) {
            const float4* H1 = (const float4*)(h1 + (size_t)node * D);
            const float4* H2 = (const float4*)(h2 + (size_t)node * D);
            #pragma unroll 8
            for (int u = 0; u < 16; ++u) {
                float4 v = H1[u];
                stage4h(Bw, nt_e, n_e, xe, u * 4, v.x, v.y, v.z, v.w);
            }
            #pragma unroll 8
            for (int u = 0; u < 16; ++u) {
                float4 v = H2[u];
                stage4h(Bw, nt_e, n_e, xe, 64 + u * 4, v.x, v.y, v.z, v.w);
            }
        } else {
            #pragma unroll 8
            for (int u = 0; u < 32; ++u)
                stage4h(Bw, nt_e, n_e, xe, u * 4, 0.f, 0.f, 0.f, 0.f);
        }
        __syncwarp();

        float acc[8][4][4];

        // ---- P pass: A1, K=128
        #pragma unroll
        for (int mt = 0; mt < 8; ++mt)
            #pragma unroll
            for (int nt = 0; nt < 4; ++nt)
                #pragma unroll
                for (int r = 0; r < 4; ++r) acc[mt][nt][r] = 0.f;

        #pragma unroll 1
        for (int kt = 0; kt < 8; ++kt) {
            uint2 bh[4];
            #pragma unroll
            for (int nt = 0; nt < 4; ++nt)
                bh[nt] = ((const uint2*)Bw)[(nt * 8 + kt) * 32 + (lane ^ (2 * nt + lq))];
            #pragma unroll
            for (int mt = 0; mt < 8; ++mt) {
                uint4 ah = A1[(mt * 8 + kt) * 32 + lane];
                #pragma unroll
                for (int nt = 0; nt < 4; ++nt) mma_f16(acc[mt][nt], ah, bh[nt]);
            }
        }
        #pragma unroll
        for (int nt = 0; nt < 4; ++nt) {
            int n0 = nb + nt * 8 + tig * 2, n1 = n0 + 1;
            #pragma unroll
            for (int mt = 0; mt < 8; ++mt) {
                int r0 = mt * 16 + gid, r1 = r0 + 8;
                if (n0 < n) {
                    g_P[(size_t)n0 * H + r0] = __float2half_rn(acc[mt][nt][0] + b1r0[mt]);
                    g_P[(size_t)n0 * H + r1] = __float2half_rn(acc[mt][nt][2] + b1r1[mt]);
                }
                if (n1 < n) {
                    g_P[(size_t)n1 * H + r0] = __float2half_rn(acc[mt][nt][1] + b1r0[mt]);
                    g_P[(size_t)n1 * H + r1] = __float2half_rn(acc[mt][nt][3] + b1r1[mt]);
                }
            }
        }

        // ---- Q pass: A2, K=64 (B slabs kt 0..3 hold h1)
        #pragma unroll
        for (int mt = 0; mt < 8; ++mt)
            #pragma unroll
            for (int nt = 0; nt < 4; ++nt)
                #pragma unroll
                for (int r = 0; r < 4; ++r) acc[mt][nt][r] = 0.f;

        #pragma unroll 1
        for (int kt = 0; kt < 4; ++kt) {
            uint2 bh[4];
            #pragma unroll
            for (int nt = 0; nt < 4; ++nt)
                bh[nt] = ((const uint2*)Bw)[(nt * 8 + kt) * 32 + (lane ^ (2 * nt + lq))];
            #pragma unroll
            for (int mt = 0; mt < 8; ++mt) {
                uint4 ah = A2[(mt * 4 + kt) * 32 + lane];
                #pragma unroll
                for (int nt = 0; nt < 4; ++nt) mma_f16(acc[mt][nt], ah, bh[nt]);
            }
        }
        #pragma unroll
        for (int nt = 0; nt < 4; ++nt) {
            int n0 = nb + nt * 8 + tig * 2, n1 = n0 + 1;
            #pragma unroll
            for (int mt = 0; mt < 8; ++mt) {
                int r0 = mt * 16 + gid, r1 = r0 + 8;
                if (n0 < n) {
                    g_Q[(size_t)n0 * H + r0] = __float2half_rn(acc[mt][nt][0]);
                    g_Q[(size_t)n0 * H + r1] = __float2half_rn(acc[mt][nt][2]);
                }
                if (n1 < n) {
                    g_Q[(size_t)n1 * H + r0] = __float2half_rn(acc[mt][nt][1]);
                    g_Q[(size_t)n1 * H + r1] = __float2half_rn(acc[mt][nt][3]);
                }
            }
        }
    }
}

// ---------------------------------------------------------------------------
// Edge kernel: R8 config (256 threads, 8 independent warps, 1-tile tickets),
// staging sigmoids in pure half2 (tanh.approx.f16x2) — no unpack/repack.
// ---------------------------------------------------------------------------
#define E_A   0                 // 32 KB
#define E_B   32768             // 8 warps x 8 KB
#define E_B2S 98304
#define E_W3S 98816
#define EDGE_SMEM_BYTES 99840

__global__ void __launch_bounds__(256) edge_kernel(
    const int* __restrict__ src, const int* __restrict__ dst,
    const float* __restrict__ W2, const float* __restrict__ b2,
    const float* __restrict__ W3, const float* __restrict__ b3,
    float* __restrict__ out, int E, int n)
{
    extern __shared__ char smc[];
    uint4* Ahi = (uint4*)(smc + E_A);
    float* b2s = (float*)(smc + E_B2S);
    float* w3s = (float*)(smc + E_W3S);

    const int t = threadIdx.x, lane = t & 31, w = t >> 5;
    const int gid = lane >> 2, tig = lane & 3;

    if (blockIdx.x == 0 && t == 0) g_ctr_pre = 0;    // reset for next replay

    // Build W2 fp16 fragments once.
    {
        float* scr = (float*)(smc + E_B);
        for (int chunk = 0; chunk < 4; ++chunk) {
            __syncthreads();
            for (int i = t; i < 1024; i += 256)
                ((float4*)scr)[i] = ((const float4*)W2)[chunk * 1024 + i];
            __syncthreads();
            build_frags_h(scr, Ahi, chunk * 2, 8, t, 256);
        }
    }
    if (t < 128) { b2s[t] = b2[t]; w3s[t] = W3[t]; }
    __syncthreads();

    float b2r0[8], b2r1[8], w3r0[8], w3r1[8];
    #pragma unroll
    for (int mt = 0; mt < 8; ++mt) {
        b2r0[mt] = b2s[mt * 16 + gid];
        b2r1[mt] = b2s[mt * 16 + gid + 8];
        w3r0[mt] = w3s[mt * 16 + gid];
        w3r1[mt] = w3s[mt * 16 + gid + 8];
    }
    const float b3v = b3[0];

    uint32_t* Bw = (uint32_t*)(smc + E_B + w * 8192);
    const int e = lane, nt_e = e >> 3, n_e = e & 7, xe = e >> 2;
    const int lq = lane >> 4;
    const int ntiles = (E + 31) >> 5;

    for (;;) {
        int tile;
        if (lane == 0) tile = atomicAdd(&g_ctr_edge, 1);
        tile = __shfl_sync(0xffffffffu, tile, 0);
        if (tile >= ntiles) break;
        const int e0 = tile * 32;
        const int ge = e0 + e;
        __syncwarp();

        // stage z1 = sigmoid(P[src]+Q[dst]) — all-half2 pipeline, output words
        // are already the packed f16x2 fragment entries
        if (ge < E) {
            int s = min(max(src[ge], 0), n - 1);
            int d = min(max(dst[ge], 0), n - 1);
            const uint4* Pp = (const uint4*)(g_P + (size_t)s * H);
            const uint4* Qp = (const uint4*)(g_Q + (size_t)d * H);
            #pragma unroll 4
            for (int u = 0; u < 16; ++u) {
                uint4 pv = Pp[u], qv = Qp[u];
                uint32_t r01 = sigt2u(pv.x, qv.x);
                uint32_t r23 = sigt2u(pv.y, qv.y);
                uint32_t r45 = sigt2u(pv.z, qv.z);
                uint32_t r67 = sigt2u(pv.w, qv.w);
                stage4u(Bw, nt_e, n_e, xe, u * 8,     r01, r23);
                stage4u(Bw, nt_e, n_e, xe, u * 8 + 4, r45, r67);
            }
        } else {
            #pragma unroll 8
            for (int u = 0; u < 32; ++u)
                stage4u(Bw, nt_e, n_e, xe, u * 4, 0u, 0u);
        }
        __syncwarp();

        float acc[8][4][4];
        #pragma unroll
        for (int mt = 0; mt < 8; ++mt)
            #pragma unroll
            for (int nt = 0; nt < 4; ++nt)
                #pragma unroll
                for (int r = 0; r < 4; ++r) acc[mt][nt][r] = 0.f;

        #pragma unroll 1
        for (int kt = 0; kt < 8; ++kt) {
            uint2 bh[4];
            #pragma unroll
            for (int nt = 0; nt < 4; ++nt)
                bh[nt] = ((const uint2*)Bw)[(nt * 8 + kt) * 32 + (lane ^ (2 * nt + lq))];
            #pragma unroll
            for (int mt = 0; mt < 8; ++mt) {
                uint4 ah = Ahi[(mt * 8 + kt) * 32 + lane];
                #pragma unroll
                for (int nt = 0; nt < 4; ++nt) mma_f16(acc[mt][nt], ah, bh[nt]);
            }
        }

        // epilogue (fp32 sigt — no error budget to spend here)
        #pragma unroll
        for (int nt = 0; nt < 4; ++nt) {
            float s0 = 0.f, s1 = 0.f;
            #pragma unroll
            for (int mt = 0; mt < 8; ++mt) {
                s0 += sigt(acc[mt][nt][0] + b2r0[mt]) * w3r0[mt]
                    + sigt(acc[mt][nt][2] + b2r1[mt]) * w3r1[mt];
                s1 += sigt(acc[mt][nt][1] + b2r0[mt]) * w3r0[mt]
                    + sigt(acc[mt][nt][3] + b2r1[mt]) * w3r1[mt];
            }
            #pragma unroll
            for (int off = 4; off <= 16; off <<= 1) {
                s0 += __shfl_xor_sync(0xffffffffu, s0, off);
                s1 += __shfl_xor_sync(0xffffffffu, s1, off);
            }
            if (gid == 0) {
                int go = e0 + nt * 8 + tig * 2;
                if (go + 1 < E)
                    *(float2*)(out + go) = make_float2(s0 + b3v, s1 + b3v);
                else if (go < E)
                    out[go] = s0 + b3v;
            }
        }
    }
}

extern "C" void kernel_launch(void* const* d_in, const int* in_sizes, int n_in,
                              void* d_out, int out_size)
{
    const float* h1 = (const float*)d_in[0];
    const float* h2 = (const float*)d_in[1];
    const int* src = (const int*)d_in[2];
    const int* dst = (const int*)d_in[3];
    const float* W1 = (const float*)d_in[4];
    const float* b1 = (const float*)d_in[5];
    const float* W2 = (const float*)d_in[6];
    const float* b2 = (const float*)d_in[7];
    const float* W3 = (const float*)d_in[8];
    const float* b3 = (const float*)d_in[9];
    float* out = (float*)d_out;

    const int n = in_sizes[0] / D;
    const int E = in_sizes[2];

    cudaFuncSetAttribute(precompute_kernel,
                         cudaFuncAttributeMaxDynamicSharedMemorySize, PRE_SMEM_BYTES);
    cudaFuncSetAttribute(edge_kernel,
                         cudaFuncAttributeMaxDynamicSharedMemorySize, EDGE_SMEM_BYTES);

    precompute_kernel<<<148, 256, PRE_SMEM_BYTES>>>(h1, h2, W1, b1, n);
    edge_kernel<<<148, 256, EDGE_SMEM_BYTES>>>(src, dst, W2, b2, W3, b3, out, E, n);
}

// round 11
// speedup vs baseline: 1.1414x; 1.0106x over previous
#include <cuda_runtime.h>
#include <cuda_fp16.h>
#include <cstdint>

#define D 64
#define H 128
#define NMAX 50048

// Node-factored layer-1 preactivations, fp16 (halves gather traffic)
__device__ __align__(16) __half g_P[(size_t)NMAX * H];
__device__ __align__(16) __half g_Q[(size_t)NMAX * H];
__device__ int g_ctr_pre;    // reset by edge_kernel (for next replay)
__device__ int g_ctr_edge;   // reset by precompute_kernel (runs first)

__device__ __forceinline__ float sigt(float x) {
    float t;
    asm("tanh.approx.f32 %0, %1;" : "=f"(t) : "f"(x * 0.5f));
    return fmaf(t, 0.5f, 0.5f);
}
// half2 sigmoid: sig(x) = 0.5*tanh(0.5x)+0.5, fully in f16x2
__device__ __forceinline__ uint32_t sigt2u(uint32_t p, uint32_t q) {
    __half2 x = __hadd2(*(__half2*)&p, *(__half2*)&q);
    const __half2 hhalf = __floats2half2_rn(0.5f, 0.5f);
    __half2 xh = __hmul2(x, hhalf);
    uint32_t tu;
    asm("tanh.approx.f16x2 %0, %1;" : "=r"(tu) : "r"(*(uint32_t*)&xh));
    __half2 r = __hfma2(*(__half2*)&tu, hhalf, hhalf);
    return *(uint32_t*)&r;
}
__device__ __forceinline__ uint32_t f16x2(float lo, float hi) {
    __half2 h = __floats2half2_rn(lo, hi);
    return *(uint32_t*)&h;
}

// fp16 m16n8k16 row.col MMA, fp32 accum
__device__ __forceinline__ void mma_f16(float* c, uint4 a, uint2 b) {
    asm volatile(
        "mma.sync.aligned.m16n8k16.row.col.f32.f16.f16.f32 "
        "{%0,%1,%2,%3}, {%4,%5,%6,%7}, {%8,%9}, {%0,%1,%2,%3};"
        : "+f"(c[0]), "+f"(c[1]), "+f"(c[2]), "+f"(c[3])
        : "r"(a.x), "r"(a.y), "r"(a.z), "r"(a.w), "r"(b.x), "r"(b.y));
}

// Build fp16 A-fragments (m16n8k16 row-major layout, validated R5-R10) from a
// 32-row fp32 scratch slab, ncols = nkt*16.
__device__ __forceinline__ void build_frags_h(const float* scr, uint4* A,
                                              int mt_base, int nkt, int t, int nth)
{
    const int ncols = nkt * 16;
    for (int fid = t; fid < 64 * nkt; fid += nth) {
        int fl = fid & 31;
        int kt = (fid >> 5) % nkt;
        int mtl = fid / (32 * nkt);
        int fg = fl >> 2, ft = fl & 3;
        int lr0 = mtl * 16 + fg, lr1 = lr0 + 8;
        int k0 = kt * 16 + ft * 2;
        uint4 hi;
        hi.x = f16x2(scr[lr0 * ncols + k0],     scr[lr0 * ncols + k0 + 1]);
        hi.y = f16x2(scr[lr1 * ncols + k0],     scr[lr1 * ncols + k0 + 1]);
        hi.z = f16x2(scr[lr0 * ncols + k0 + 8], scr[lr0 * ncols + k0 + 9]);
        hi.w = f16x2(scr[lr1 * ncols + k0 + 8], scr[lr1 * ncols + k0 + 9]);
        A[((mt_base + mtl) * nkt + kt) * 32 + fl] = hi;
    }
}

// Store two packed f16x2 words (values k..k+3, k%4==0) for fragment-column nn
// of group nt. Writer XOR = e>>2; reader uses lane ^ (2*nt + lane>>4). R6-R10.
__device__ __forceinline__ void stage4u(uint32_t* B, int nt, int nn, int xe, int k,
                                        uint32_t h01, uint32_t h23)
{
    int kt = k >> 4, kq = (k & 7) >> 1, reg = (k >> 3) & 1;
    int l0 = (nn * 4 + kq) ^ xe, l1 = (nn * 4 + kq + 1) ^ xe;
    int base = (nt * 8 + kt) * 64;
    B[base + l0 * 2 + reg] = h01;
    B[base + l1 * 2 + reg] = h23;
}
__device__ __forceinline__ void stage4h(uint32_t* B, int nt, int nn, int xe, int k,
                                        float z0, float z1, float z2, float z3)
{
    stage4u(B, nt, nn, xe, k, f16x2(z0, z1), f16x2(z2, z3));
}

// ---------------------------------------------------------------------------
// Precompute: P[n] = b1 + [Wa | Wc+Wd] @ [h1;h2],  Q[n] = Wb @ h1  (fp16 out)
// 256 threads, 8 independent warps, 32 nodes per warp-tile, fp16 HMMA.
// (unchanged from R10)
// ---------------------------------------------------------------------------
#define P_A1 0                  // 32 KB
#define P_A2 32768              // 16 KB
#define P_B  49152              // 8 warps x 8 KB
#define P_B1S 114688
#define PRE_SMEM_BYTES 115712

__global__ void __launch_bounds__(256) precompute_kernel(
    const float* __restrict__ h1, const float* __restrict__ h2,
    const float* __restrict__ W1, const float* __restrict__ b1, int n)
{
    extern __shared__ char smc[];
    uint4* A1 = (uint4*)(smc + P_A1);
    uint4* A2 = (uint4*)(smc + P_A2);
    float* b1s = (float*)(smc + P_B1S);

    const int t = threadIdx.x, lane = t & 31, w = t >> 5;
    const int gid = lane >> 2, tig = lane & 3;

    if (blockIdx.x == 0 && t == 0) g_ctr_edge = 0;   // reset for edge_kernel

    {
        float* scr = (float*)(smc + P_B);
        for (int chunk = 0; chunk < 4; ++chunk) {
            const int R0 = chunk * 32;
            __syncthreads();
            for (int idx = t; idx < 4096; idx += 256) {
                int r = idx >> 7, k = idx & 127;
                float v;
                if (k < 64) v = W1[(R0 + r) * 256 + k];
                else        v = W1[(R0 + r) * 256 + 64 + k] + W1[(R0 + r) * 256 + 128 + k];
                scr[r * 128 + k] = v;
            }
            __syncthreads();
            build_frags_h(scr, A1, chunk * 2, 8, t, 256);
        }
        for (int chunk = 0; chunk < 4; ++chunk) {
            const int R0 = chunk * 32;
            __syncthreads();
            for (int idx = t; idx < 2048; idx += 256) {
                int r = idx >> 6, k = idx & 63;
                scr[r * 64 + k] = W1[(R0 + r) * 256 + 64 + k];
            }
            __syncthreads();
            build_frags_h(scr, A2, chunk * 2, 4, t, 256);
        }
    }
    if (t < 128) b1s[t] = b1[t];
    __syncthreads();

    float b1r0[8], b1r1[8];
    #pragma unroll
    for (int mt = 0; mt < 8; ++mt) {
        b1r0[mt] = b1s[mt * 16 + gid];
        b1r1[mt] = b1s[mt * 16 + gid + 8];
    }

    uint32_t* Bw = (uint32_t*)(smc + P_B + w * 8192);
    const int e = lane, nt_e = e >> 3, n_e = e & 7, xe = e >> 2;
    const int lq = lane >> 4;
    const int ntiles = (n + 31) >> 5;

    for (;;) {
        int tile;
        if (lane == 0) tile = atomicAdd(&g_ctr_pre, 1);
        tile = __shfl_sync(0xffffffffu, tile, 0);
        if (tile >= ntiles) break;
        const int nb = tile * 32;
        const int node = nb + e;
        __syncwarp();

        if (node < n) {
            const float4* H1 = (const float4*)(h1 + (size_t)node * D);
            const float4* H2 = (const float4*)(h2 + (size_t)node * D);
            #pragma unroll 8
            for (int u = 0; u < 16; ++u) {
                float4 v = H1[u];
                stage4h(Bw, nt_e, n_e, xe, u * 4, v.x, v.y, v.z, v.w);
            }
            #pragma unroll 8
            for (int u = 0; u < 16; ++u) {
                float4 v = H2[u];
                stage4h(Bw, nt_e, n_e, xe, 64 + u * 4, v.x, v.y, v.z, v.w);
            }
        } else {
            #pragma unroll 8
            for (int u = 0; u < 32; ++u)
                stage4h(Bw, nt_e, n_e, xe, u * 4, 0.f, 0.f, 0.f, 0.f);
        }
        __syncwarp();

        float acc[8][4][4];

        // ---- P pass: A1, K=128
        #pragma unroll
        for (int mt = 0; mt < 8; ++mt)
            #pragma unroll
            for (int nt = 0; nt < 4; ++nt)
                #pragma unroll
                for (int r = 0; r < 4; ++r) acc[mt][nt][r] = 0.f;

        #pragma unroll 1
        for (int kt = 0; kt < 8; ++kt) {
            uint2 bh[4];
            #pragma unroll
            for (int nt = 0; nt < 4; ++nt)
                bh[nt] = ((const uint2*)Bw)[(nt * 8 + kt) * 32 + (lane ^ (2 * nt + lq))];
            #pragma unroll
            for (int mt = 0; mt < 8; ++mt) {
                uint4 ah = A1[(mt * 8 + kt) * 32 + lane];
                #pragma unroll
                for (int nt = 0; nt < 4; ++nt) mma_f16(acc[mt][nt], ah, bh[nt]);
            }
        }
        #pragma unroll
        for (int nt = 0; nt < 4; ++nt) {
            int n0 = nb + nt * 8 + tig * 2, n1 = n0 + 1;
            #pragma unroll
            for (int mt = 0; mt < 8; ++mt) {
                int r0 = mt * 16 + gid, r1 = r0 + 8;
                if (n0 < n) {
                    g_P[(size_t)n0 * H + r0] = __float2half_rn(acc[mt][nt][0] + b1r0[mt]);
                    g_P[(size_t)n0 * H + r1] = __float2half_rn(acc[mt][nt][2] + b1r1[mt]);
                }
                if (n1 < n) {
                    g_P[(size_t)n1 * H + r0] = __float2half_rn(acc[mt][nt][1] + b1r0[mt]);
                    g_P[(size_t)n1 * H + r1] = __float2half_rn(acc[mt][nt][3] + b1r1[mt]);
                }
            }
        }

        // ---- Q pass: A2, K=64 (B slabs kt 0..3 hold h1)
        #pragma unroll
        for (int mt = 0; mt < 8; ++mt)
            #pragma unroll
            for (int nt = 0; nt < 4; ++nt)
                #pragma unroll
                for (int r = 0; r < 4; ++r) acc[mt][nt][r] = 0.f;

        #pragma unroll 1
        for (int kt = 0; kt < 4; ++kt) {
            uint2 bh[4];
            #pragma unroll
            for (int nt = 0; nt < 4; ++nt)
                bh[nt] = ((const uint2*)Bw)[(nt * 8 + kt) * 32 + (lane ^ (2 * nt + lq))];
            #pragma unroll
            for (int mt = 0; mt < 8; ++mt) {
                uint4 ah = A2[(mt * 4 + kt) * 32 + lane];
                #pragma unroll
                for (int nt = 0; nt < 4; ++nt) mma_f16(acc[mt][nt], ah, bh[nt]);
            }
        }
        #pragma unroll
        for (int nt = 0; nt < 4; ++nt) {
            int n0 = nb + nt * 8 + tig * 2, n1 = n0 + 1;
            #pragma unroll
            for (int mt = 0; mt < 8; ++mt) {
                int r0 = mt * 16 + gid, r1 = r0 + 8;
                if (n0 < n) {
                    g_Q[(size_t)n0 * H + r0] = __float2half_rn(acc[mt][nt][0]);
                    g_Q[(size_t)n0 * H + r1] = __float2half_rn(acc[mt][nt][2]);
                }
                if (n1 < n) {
                    g_Q[(size_t)n1 * H + r0] = __float2half_rn(acc[mt][nt][1]);
                    g_Q[(size_t)n1 * H + r1] = __float2half_rn(acc[mt][nt][3]);
                }
            }
        }
    }
}

// ---------------------------------------------------------------------------
// Edge kernel: software-pipelined. Per-warp double-buffered B fragments;
// while tile t's MMA chain runs, tile t+1's gather is issued (depth-2
// prefetch) and sigmoid+staged between MMA kt-steps.
// ---------------------------------------------------------------------------
#define E_A   0                 // 32 KB
#define E_B   32768             // 8 warps x 2 bufs x 8 KB = 128 KB
#define E_B2S 163840
#define E_W3S 164352
#define EDGE_SMEM_BYTES 164864

__global__ void __launch_bounds__(256) edge_kernel(
    const int* __restrict__ src, const int* __restrict__ dst,
    const float* __restrict__ W2, const float* __restrict__ b2,
    const float* __restrict__ W3, const float* __restrict__ b3,
    float* __restrict__ out, int E, int n)
{
    extern __shared__ char smc[];
    uint4* Ahi = (uint4*)(smc + E_A);
    float* b2s = (float*)(smc + E_B2S);
    float* w3s = (float*)(smc + E_W3S);

    const int t = threadIdx.x, lane = t & 31, w = t >> 5;
    const int gid = lane >> 2, tig = lane & 3;

    if (blockIdx.x == 0 && t == 0) g_ctr_pre = 0;    // reset for next replay

    // Build W2 fp16 fragments once (scratch reuses B region).
    {
        float* scr = (float*)(smc + E_B);
        for (int chunk = 0; chunk < 4; ++chunk) {
            __syncthreads();
            for (int i = t; i < 1024; i += 256)
                ((float4*)scr)[i] = ((const float4*)W2)[chunk * 1024 + i];
            __syncthreads();
            build_frags_h(scr, Ahi, chunk * 2, 8, t, 256);
        }
    }
    if (t < 128) { b2s[t] = b2[t]; w3s[t] = W3[t]; }
    __syncthreads();

    float b2r0[8], b2r1[8], w3r0[8], w3r1[8];
    #pragma unroll
    for (int mt = 0; mt < 8; ++mt) {
        b2r0[mt] = b2s[mt * 16 + gid];
        b2r1[mt] = b2s[mt * 16 + gid + 8];
        w3r0[mt] = w3s[mt * 16 + gid];
        w3r1[mt] = w3s[mt * 16 + gid + 8];
    }
    const float b3v = b3[0];

    uint32_t* Bw0 = (uint32_t*)(smc + E_B + w * 16384);
    uint32_t* Bw1 = Bw0 + 2048;
    const int e = lane, nt_e = e >> 3, n_e = e & 7, xe = e >> 2;
    const int lq = lane >> 4;
    const int ntiles = (E + 31) >> 5;

    int tile;
    if (lane == 0) tile = atomicAdd(&g_ctr_edge, 1);
    tile = __shfl_sync(0xffffffffu, tile, 0);

    if (tile < ntiles) {
        // ---- prologue: stage tile's B fully into Bw0
        {
            const int ge = tile * 32 + e;
            if (ge < E) {
                int s = min(max(src[ge], 0), n - 1);
                int d = min(max(dst[ge], 0), n - 1);
                const uint4* Pp = (const uint4*)(g_P + (size_t)s * H);
                const uint4* Qp = (const uint4*)(g_Q + (size_t)d * H);
                #pragma unroll 4
                for (int u = 0; u < 16; ++u) {
                    uint4 pv = Pp[u], qv = Qp[u];
                    stage4u(Bw0, nt_e, n_e, xe, u * 8,
                            sigt2u(pv.x, qv.x), sigt2u(pv.y, qv.y));
                    stage4u(Bw0, nt_e, n_e, xe, u * 8 + 4,
                            sigt2u(pv.z, qv.z), sigt2u(pv.w, qv.w));
                }
            } else {
                #pragma unroll 8
                for (int u = 0; u < 32; ++u)
                    stage4u(Bw0, nt_e, n_e, xe, u * 4, 0u, 0u);
            }
        }

        int buf = 0;
        for (;;) {
            int next;
            if (lane == 0) next = atomicAdd(&g_ctr_edge, 1);
            next = __shfl_sync(0xffffffffu, next, 0);
            const bool have_next = next < ntiles;

            // next tile's gather pointers (OOB edges read node 0; columns
            // are finite junk, discarded by the epilogue guard)
            const uint4* Pp2 = (const uint4*)g_P;
            const uint4* Qp2 = (const uint4*)g_Q;
            if (have_next) {
                int ge2 = next * 32 + e;
                if (ge2 < E) {
                    int s2 = min(max(src[ge2], 0), n - 1);
                    int d2 = min(max(dst[ge2], 0), n - 1);
                    Pp2 = (const uint4*)(g_P + (size_t)s2 * H);
                    Qp2 = (const uint4*)(g_Q + (size_t)d2 * H);
                }
            }

            uint32_t* Bcur = buf ? Bw1 : Bw0;
            uint32_t* Bnxt = buf ? Bw0 : Bw1;
            __syncwarp();   // prior STS (to Bcur) visible before LDS below

            float acc[8][4][4];
            #pragma unroll
            for (int mt = 0; mt < 8; ++mt)
                #pragma unroll
                for (int nt = 0; nt < 4; ++nt)
                    #pragma unroll
                    for (int r = 0; r < 4; ++r) acc[mt][nt][r] = 0.f;

            // depth-2 prefetch registers (kt parity)
            uint4 p0[2], p1[2], q0[2], q1[2];
            if (have_next) {
                p0[0] = Pp2[0]; p1[0] = Pp2[1];
                q0[0] = Qp2[0]; q1[0] = Qp2[1];
            }

            #pragma unroll
            for (int kt = 0; kt < 8; ++kt) {
                const int cur = kt & 1, nb2 = cur ^ 1;
                if (have_next && kt < 7) {
                    p0[nb2] = Pp2[2 * kt + 2]; p1[nb2] = Pp2[2 * kt + 3];
                    q0[nb2] = Qp2[2 * kt + 2]; q1[nb2] = Qp2[2 * kt + 3];
                }

                uint2 bh[4];
                #pragma unroll
                for (int nt = 0; nt < 4; ++nt)
                    bh[nt] = ((const uint2*)Bcur)[(nt * 8 + kt) * 32 + (lane ^ (2 * nt + lq))];
                #pragma unroll
                for (int mt = 0; mt < 8; ++mt) {
                    uint4 ah = Ahi[(mt * 8 + kt) * 32 + lane];
                    #pragma unroll
                    for (int nt = 0; nt < 4; ++nt) mma_f16(acc[mt][nt], ah, bh[nt]);
                }

                if (have_next) {
                    stage4u(Bnxt, nt_e, n_e, xe, kt * 16,
                            sigt2u(p0[cur].x, q0[cur].x), sigt2u(p0[cur].y, q0[cur].y));
                    stage4u(Bnxt, nt_e, n_e, xe, kt * 16 + 4,
                            sigt2u(p0[cur].z, q0[cur].z), sigt2u(p0[cur].w, q0[cur].w));
                    stage4u(Bnxt, nt_e, n_e, xe, kt * 16 + 8,
                            sigt2u(p1[cur].x, q1[cur].x), sigt2u(p1[cur].y, q1[cur].y));
                    stage4u(Bnxt, nt_e, n_e, xe, kt * 16 + 12,
                            sigt2u(p1[cur].z, q1[cur].z), sigt2u(p1[cur].w, q1[cur].w));
                }
            }

            // ---- epilogue for current tile (fp32 sigt — keep output accuracy)
            const int e0 = tile * 32;
            #pragma unroll
            for (int nt = 0; nt < 4; ++nt) {
                float s0 = 0.f, s1 = 0.f;
                #pragma unroll
                for (int mt = 0; mt < 8; ++mt) {
                    s0 += sigt(acc[mt][nt][0] + b2r0[mt]) * w3r0[mt]
                        + sigt(acc[mt][nt][2] + b2r1[mt]) * w3r1[mt];
                    s1 += sigt(acc[mt][nt][1] + b2r0[mt]) * w3r0[mt]
                        + sigt(acc[mt][nt][3] + b2r1[mt]) * w3r1[mt];
                }
                #pragma unroll
                for (int off = 4; off <= 16; off <<= 1) {
                    s0 += __shfl_xor_sync(0xffffffffu, s0, off);
                    s1 += __shfl_xor_sync(0xffffffffu, s1, off);
                }
                if (gid == 0) {
                    int go = e0 + nt * 8 + tig * 2;
                    if (go + 1 < E)
                        *(float2*)(out + go) = make_float2(s0 + b3v, s1 + b3v);
                    else if (go < E)
                        out[go] = s0 + b3v;
                }
            }

            if (!have_next) break;
            tile = next;
            buf ^= 1;
        }
    }
}

extern "C" void kernel_launch(void* const* d_in, const int* in_sizes, int n_in,
                              void* d_out, int out_size)
{
    const float* h1 = (const float*)d_in[0];
    const float* h2 = (const float*)d_in[1];
    const int* src = (const int*)d_in[2];
    const int* dst = (const int*)d_in[3];
    const float* W1 = (const float*)d_in[4];
    const float* b1 = (const float*)d_in[5];
    const float* W2 = (const float*)d_in[6];
    const float* b2 = (const float*)d_in[7];
    const float* W3 = (const float*)d_in[8];
    const float* b3 = (const float*)d_in[9];
    float* out = (float*)d_out;

    const int n = in_sizes[0] / D;
    const int E = in_sizes[2];

    cudaFuncSetAttribute(precompute_kernel,
                         cudaFuncAttributeMaxDynamicSharedMemorySize, PRE_SMEM_BYTES);
    cudaFuncSetAttribute(edge_kernel,
                         cudaFuncAttributeMaxDynamicSharedMemorySize, EDGE_SMEM_BYTES);

    precompute_kernel<<<148, 256, PRE_SMEM_BYTES>>>(h1, h2, W1, b1, n);
    edge_kernel<<<148, 256, EDGE_SMEM_BYTES>>>(src, dst, W2, b2, W3, b3, out, E, n);
}